// round 3
// baseline (speedup 1.0000x reference)
#include <cuda_runtime.h>

// Problem shapes (fixed instance: inputs [4,64,512,512] f32, targets [4,512,512] int32
// (JAX x64 disabled -> int64 request materializes as int32), group_ids [64] i32,
// scalar f32 output).
#define B_     4
#define C_     64
#define H_     512
#define W_     512
#define HW_    (H_ * W_)          // 262144
#define NPIX_  (B_ * HW_)         // 1048576
#define BLOCK_ 256
#define NBLK_  (NPIX_ / BLOCK_)   // 4096
#define IGNORE_IDX 255

// Scratch for per-block partials (device globals: no allocation allowed).
__device__ float g_psum[NBLK_];
__device__ float g_pcnt[NBLK_];

__global__ void __launch_bounds__(BLOCK_)
uni_ce2d_main(const float* __restrict__ inp,
              const int* __restrict__ tgt,
              const int* __restrict__ gid)
{
    __shared__ int sgid[C_];
    if (threadIdx.x < C_) sgid[threadIdx.x] = gid[threadIdx.x];
    __syncthreads();

    const int i = blockIdx.x * BLOCK_ + threadIdx.x;   // pixel index in [0, NPIX_)
    const int b = i >> 18;                              // i / HW_  (HW_ = 2^18)
    const int p = i & (HW_ - 1);                        // i % HW_

    const float* base = inp + (size_t)b * C_ * HW_ + p;

    // Load all 64 channel values (coalesced across the warp per channel).
    float v[C_];
#pragma unroll
    for (int c = 0; c < C_; ++c)
        v[c] = base[(size_t)c * HW_];

    // Per-pixel max (global max cancels algebraically; per-pixel max is
    // mathematically identical and numerically safe).
    float m = v[0];
#pragma unroll
    for (int c = 1; c < C_; ++c)
        m = fmaxf(m, v[c]);

    const int t = tgt[i];
    const bool valid = (t != IGNORE_IDX);
    const int tt = valid ? t : 0;

    float stot = 0.0f, sgrp = 0.0f;
#pragma unroll
    for (int c = 0; c < C_; ++c) {
        float e = __expf(v[c] - m);
        stot += e;
        sgrp += (sgid[c] == tt) ? e : 0.0f;
    }

    float lp = __logf(sgrp) - __logf(stot);
    float contrib = valid ? -lp : 0.0f;
    float cnt = valid ? 1.0f : 0.0f;

    // Warp reduce
#pragma unroll
    for (int o = 16; o > 0; o >>= 1) {
        contrib += __shfl_down_sync(0xFFFFFFFFu, contrib, o);
        cnt     += __shfl_down_sync(0xFFFFFFFFu, cnt, o);
    }

    // Block reduce via shared
    __shared__ float ssum[BLOCK_ / 32];
    __shared__ float scnt[BLOCK_ / 32];
    const int lane = threadIdx.x & 31;
    const int wid  = threadIdx.x >> 5;
    if (lane == 0) { ssum[wid] = contrib; scnt[wid] = cnt; }
    __syncthreads();

    if (wid == 0) {
        float s = (lane < BLOCK_ / 32) ? ssum[lane] : 0.0f;
        float c = (lane < BLOCK_ / 32) ? scnt[lane] : 0.0f;
#pragma unroll
        for (int o = 4; o > 0; o >>= 1) {
            s += __shfl_down_sync(0xFFFFFFFFu, s, o);
            c += __shfl_down_sync(0xFFFFFFFFu, c, o);
        }
        if (lane == 0) { g_psum[blockIdx.x] = s; g_pcnt[blockIdx.x] = c; }
    }
}

__global__ void __launch_bounds__(1024)
uni_ce2d_reduce(float* __restrict__ out)
{
    double s = 0.0, c = 0.0;
    for (int i = threadIdx.x; i < NBLK_; i += 1024) {
        s += (double)g_psum[i];
        c += (double)g_pcnt[i];
    }
#pragma unroll
    for (int o = 16; o > 0; o >>= 1) {
        s += __shfl_down_sync(0xFFFFFFFFu, s, o);
        c += __shfl_down_sync(0xFFFFFFFFu, c, o);
    }
    __shared__ double ds[32], dc[32];
    const int lane = threadIdx.x & 31;
    const int wid  = threadIdx.x >> 5;
    if (lane == 0) { ds[wid] = s; dc[wid] = c; }
    __syncthreads();
    if (wid == 0) {
        double ss = (lane < 32) ? ds[lane] : 0.0;
        double cc = (lane < 32) ? dc[lane] : 0.0;
#pragma unroll
        for (int o = 16; o > 0; o >>= 1) {
            ss += __shfl_down_sync(0xFFFFFFFFu, ss, o);
            cc += __shfl_down_sync(0xFFFFFFFFu, cc, o);
        }
        if (lane == 0) {
            double denom = (cc > 1.0) ? cc : 1.0;
            out[0] = (float)(ss / denom);
        }
    }
}

extern "C" void kernel_launch(void* const* d_in, const int* in_sizes, int n_in,
                              void* d_out, int out_size)
{
    const float* inp = (const float*)d_in[0];
    const int*   tgt = (const int*)d_in[1];
    const int*   gid = (const int*)d_in[2];
    float*       out = (float*)d_out;

    uni_ce2d_main<<<NBLK_, BLOCK_>>>(inp, tgt, gid);
    uni_ce2d_reduce<<<1, 1024>>>(out);
}